// round 5
// baseline (speedup 1.0000x reference)
#include <cuda_runtime.h>
#include <math.h>
#include <stdint.h>

// Problem constants
#define NODESG   116
#define HEADS    2
#define DHEAD    116
#define HIDD     256
#define BGRAPH   512
#define NTOT     (BGRAPH * NODESG)      // 59392
#define DEG      8
#define DOUT     232
#define PSTRIDE  1024                   // padded fused output width (q|k|v|s|pad)
#define NPACK    928                    // valid columns (4*232)

// GEMM tiling
#define BM 128
#define BN 128
#define BK 32
#define ASTRIDE 40                       // padded row stride in words (64-bit conflict-free)
#define STG_W   (BM * ASTRIDE)           // words per operand stage = 5120
#define GEMM_SMEM (4 * STG_W * 4)        // A0,B0,A1,B1 = 81920 B

// Scratch (device globals: no allocation allowed)
__device__ uint32_t d_At[(size_t)NTOT * HIDD];                // A as tf32 bits, k-permuted
__device__ uint32_t d_Wt[PSTRIDE * HIDD];                     // W^T padded tf32 bits, k-permuted
__device__ float d_P[(size_t)NTOT * PSTRIDE];                 // fused projections
__device__ float d_HP[(size_t)NTOT * DOUT];                   // h_proj
__device__ float d_E[NTOT];                                   // per-node mean
__device__ int   d_is32;                                      // edge_index dtype flag

// k-permutation within 8-group: position p holds source j = (p&1)? p/2+4 : p/2
__device__ __forceinline__ int kperm_src(int p) {
    return (p & 1) ? (p >> 1) + 4 : (p >> 1);
}

// ---------------------------------------------------------------------------
// helpers
// ---------------------------------------------------------------------------
__device__ __forceinline__ uint32_t f2tf32(float x) {
    uint32_t r;
    asm("cvt.rna.tf32.f32 %0, %1;" : "=r"(r) : "f"(x));
    return r;
}
__device__ __forceinline__ void mma16n8k8(float* c, const uint32_t* a, const uint32_t* b) {
    asm volatile(
        "mma.sync.aligned.m16n8k8.row.col.f32.tf32.tf32.f32 "
        "{%0,%1,%2,%3},{%4,%5,%6,%7},{%8,%9},{%0,%1,%2,%3};"
        : "+f"(c[0]), "+f"(c[1]), "+f"(c[2]), "+f"(c[3])
        : "r"(a[0]), "r"(a[1]), "r"(a[2]), "r"(a[3]), "r"(b[0]), "r"(b[1]));
}
__device__ __forceinline__ uint32_t smem_u32(const void* p) {
    uint32_t a;
    asm("{ .reg .u64 t; cvta.to.shared.u64 t, %1; cvt.u32.u64 %0, t; }" : "=r"(a) : "l"(p));
    return a;
}
__device__ __forceinline__ void cp16(uint32_t dst, const void* src) {
    asm volatile("cp.async.cg.shared.global [%0], [%1], 16;" :: "r"(dst), "l"(src));
}

// ---------------------------------------------------------------------------
// 0) edge_index dtype detection: int64 little-endian => all odd int32 words 0
// ---------------------------------------------------------------------------
__global__ void detect_kernel(const int* __restrict__ ei) {
    int j = blockIdx.x * blockDim.x + threadIdx.x;
    if (j < 4096) {
        if (ei[2 * j + 1] != 0) atomicOr(&d_is32, 1);
    }
}

// ---------------------------------------------------------------------------
// 1a) A prep: tf32-convert + k-permute h into d_At
// ---------------------------------------------------------------------------
__global__ __launch_bounds__(256) void aprep_kernel(const float* __restrict__ h) {
    int idx = blockIdx.x * blockDim.x + threadIdx.x;
    if (idx >= NTOT * HIDD) return;
    int row = idx >> 8;
    int p   = idx & 255;
    int k   = (p & ~7) | kperm_src(p & 7);
    d_At[idx] = f2tf32(h[(size_t)row * HIDD + k]);
}

// ---------------------------------------------------------------------------
// 1b) pack W^T as tf32 bits, k-permuted: d_Wt[n][k'], zero-padded n >= 928
// ---------------------------------------------------------------------------
__global__ __launch_bounds__(256) void pack_kernel(
        const float* __restrict__ Wq, const float* __restrict__ Wk,
        const float* __restrict__ Wv, const float* __restrict__ Ws) {
    int idx = blockIdx.x * blockDim.x + threadIdx.x;   // n*256 + k'
    if (idx >= PSTRIDE * HIDD) return;
    int n = idx >> 8;
    int p = idx & 255;
    int k = (p & ~7) | kperm_src(p & 7);
    float v = 0.0f;
    if      (n < 232) v = Wq[k * 232 + n];
    else if (n < 464) v = Wk[k * 232 + (n - 232)];
    else if (n < 696) v = Wv[k * 232 + (n - 464)];
    else if (n < 928) v = Ws[k * 232 + (n - 696)];
    d_Wt[idx] = f2tf32(v);
}

// ---------------------------------------------------------------------------
// 2) tf32 mma.sync GEMM: P[N,1024] = h[N,256] @ W[256,1024]
//    CTA 128x128, BK=32, 256 threads, warp tile 64x32, cp.async double buffer.
//    Both operands pre-converted tf32 bits, k-permuted -> fragment LDS.64 only.
// ---------------------------------------------------------------------------
__global__ __launch_bounds__(256, 2) void gemm_mma_kernel() {
    extern __shared__ uint32_t sm[];
    int tid  = threadIdx.x;
    int lane = tid & 31;
    int warp = tid >> 5;
    int wr = warp >> 2;          // 0..1 (M)
    int wc = warp & 3;           // 0..3 (N)
    int gid = lane >> 2;         // 0..7
    int tig = lane & 3;          // 0..3
    int brow = blockIdx.y * BM;
    int bcol = blockIdx.x * BN;

    const uint32_t* Ag = d_At + (size_t)brow * HIDD;
    const uint32_t* Bg = d_Wt + (size_t)bcol * HIDD;

    uint32_t sbase = smem_u32(sm);
    int r  = tid >> 3;           // 0..31 -> +t*32 rows
    int c4 = tid & 7;            // 16B index within 32-word row

    float c[4][4][4];
#pragma unroll
    for (int mt = 0; mt < 4; mt++)
#pragma unroll
        for (int nt = 0; nt < 4; nt++)
#pragma unroll
            for (int q = 0; q < 4; q++) c[mt][nt][q] = 0.0f;

    // prologue: stage 0
    {
#pragma unroll
        for (int t = 0; t < 4; t++) {
            int rr = r + t * 32;
            uint32_t soff = (uint32_t)(rr * ASTRIDE + c4 * 4) * 4;
            cp16(sbase + soff, Ag + (size_t)rr * HIDD + c4 * 4);
            cp16(sbase + STG_W * 4 + soff, Bg + (size_t)rr * HIDD + c4 * 4);
        }
        asm volatile("cp.async.commit_group;");
    }

    for (int ch = 0; ch < HIDD / BK; ch++) {
        if (ch < HIDD / BK - 1) {
            int kc0 = (ch + 1) * BK;
            uint32_t stg = ((ch + 1) & 1) ? 2u * STG_W * 4u : 0u;
#pragma unroll
            for (int t = 0; t < 4; t++) {
                int rr = r + t * 32;
                uint32_t soff = (uint32_t)(rr * ASTRIDE + c4 * 4) * 4;
                cp16(sbase + stg + soff, Ag + (size_t)rr * HIDD + kc0 + c4 * 4);
                cp16(sbase + stg + STG_W * 4 + soff, Bg + (size_t)rr * HIDD + kc0 + c4 * 4);
            }
            asm volatile("cp.async.commit_group;");
            asm volatile("cp.async.wait_group 1;");
        } else {
            asm volatile("cp.async.wait_group 0;");
        }
        __syncthreads();

        const uint32_t* As = sm + (ch & 1) * 2 * STG_W;
        const uint32_t* Bs = As + STG_W;

#pragma unroll
        for (int ks = 0; ks < 4; ks++) {
            // A fragments: 2 x LDS.64 per m-tile; pair = (k=tig, k=tig+4)
            uint32_t af[4][4];
#pragma unroll
            for (int mt = 0; mt < 4; mt++) {
                int r0 = wr * 64 + mt * 16 + gid;
                const uint2* pa = (const uint2*)(As + r0 * ASTRIDE + ks * 8 + 2 * tig);
                const uint2* pb = (const uint2*)(As + (r0 + 8) * ASTRIDE + ks * 8 + 2 * tig);
                uint2 ua = *pa, ub = *pb;
                af[mt][0] = ua.x; af[mt][2] = ua.y;
                af[mt][1] = ub.x; af[mt][3] = ub.y;
            }
            // B fragments: 1 x LDS.64 per n-tile
            uint32_t bf[4][2];
#pragma unroll
            for (int nt = 0; nt < 4; nt++) {
                int n0 = wc * 32 + nt * 8 + gid;
                uint2 ub = *(const uint2*)(Bs + n0 * ASTRIDE + ks * 8 + 2 * tig);
                bf[nt][0] = ub.x; bf[nt][1] = ub.y;
            }
#pragma unroll
            for (int mt = 0; mt < 4; mt++)
#pragma unroll
                for (int nt = 0; nt < 4; nt++)
                    mma16n8k8(c[mt][nt], af[mt], bf[nt]);
        }
        __syncthreads();
    }

    // Epilogue: direct store to d_P, skip padded columns >= 928
#pragma unroll
    for (int mt = 0; mt < 4; mt++) {
        int r0 = brow + wr * 64 + mt * 16 + gid;
#pragma unroll
        for (int nt = 0; nt < 4; nt++) {
            int gc = bcol + wc * 32 + nt * 8 + tig * 2;
            if (gc < NPACK) {
                float* p = d_P + (size_t)r0 * PSTRIDE + gc;
                *(float2*)p = make_float2(c[mt][nt][0], c[mt][nt][1]);
                *(float2*)(p + 8 * PSTRIDE) = make_float2(c[mt][nt][2], c[mt][nt][3]);
            }
        }
    }
}

// ---------------------------------------------------------------------------
// 3) warp-per-node edge attention + skip + per-node mean
// ---------------------------------------------------------------------------
__global__ __launch_bounds__(256) void attn_kernel(const int* __restrict__ esrc) {
    int warp = (blockIdx.x * blockDim.x + threadIdx.x) >> 5;
    int lane = threadIdx.x & 31;
    if (warp >= NTOT) return;
    int i = warp;
    int is32 = d_is32;

    const float* Pq = d_P + (size_t)i * PSTRIDE;

    float q[8];
#pragma unroll
    for (int j = 0; j < 8; j++) {
        int idx = lane + 32 * j;
        q[j] = (idx < DOUT) ? Pq[idx] : 0.0f;
    }

    int myedge = 0;
    if (lane < DEG) {
        int e = i * DEG + lane;
        myedge = is32 ? esrc[e] : esrc[2 * e];   // int64: low word
    }
    int srcs[DEG];
#pragma unroll
    for (int e = 0; e < DEG; e++) srcs[e] = __shfl_sync(0xffffffffu, myedge, e);

    const float scale = 0.09284766908852593f;    // 1/sqrt(116)
    float s0[DEG], s1[DEG];
#pragma unroll
    for (int e = 0; e < DEG; e++) {
        const float* Kp = d_P + (size_t)srcs[e] * PSTRIDE + 232;
        float a0 = 0.0f, a1 = 0.0f;
#pragma unroll
        for (int j = 0; j < 8; j++) {
            int idx = lane + 32 * j;
            if (idx < DOUT) {
                float prod = q[j] * Kp[idx];
                if (idx < DHEAD) a0 += prod; else a1 += prod;
            }
        }
#pragma unroll
        for (int off = 16; off > 0; off >>= 1) {
            a0 += __shfl_xor_sync(0xffffffffu, a0, off);
            a1 += __shfl_xor_sync(0xffffffffu, a1, off);
        }
        s0[e] = a0 * scale;
        s1[e] = a1 * scale;
    }

    float m0 = s0[0], m1 = s1[0];
#pragma unroll
    for (int e = 1; e < DEG; e++) { m0 = fmaxf(m0, s0[e]); m1 = fmaxf(m1, s1[e]); }
    float ex0[DEG], ex1[DEG], den0 = 0.0f, den1 = 0.0f;
#pragma unroll
    for (int e = 0; e < DEG; e++) {
        ex0[e] = __expf(s0[e] - m0);
        ex1[e] = __expf(s1[e] - m1);
        den0 += ex0[e]; den1 += ex1[e];
    }
    float r0 = 1.0f / (den0 + 1e-16f);
    float r1 = 1.0f / (den1 + 1e-16f);
    float al0[DEG], al1[DEG];
#pragma unroll
    for (int e = 0; e < DEG; e++) { al0[e] = ex0[e] * r0; al1[e] = ex1[e] * r1; }

    float o[8];
#pragma unroll
    for (int j = 0; j < 8; j++) o[j] = 0.0f;
#pragma unroll
    for (int e = 0; e < DEG; e++) {
        const float* Vp = d_P + (size_t)srcs[e] * PSTRIDE + 464;
#pragma unroll
        for (int j = 0; j < 8; j++) {
            int idx = lane + 32 * j;
            if (idx < DOUT) {
                float a = (idx < DHEAD) ? al0[e] : al1[e];
                o[j] += a * Vp[idx];
            }
        }
    }
    const float* Sp = d_P + (size_t)i * PSTRIDE + 696;
#pragma unroll
    for (int j = 0; j < 8; j++) {
        int idx = lane + 32 * j;
        if (idx < DOUT) o[j] += Sp[idx];
    }

    float psum = 0.0f;
#pragma unroll
    for (int j = 0; j < 8; j++) psum += o[j];
#pragma unroll
    for (int off = 16; off > 0; off >>= 1) psum += __shfl_xor_sync(0xffffffffu, psum, off);
    if (lane == 0) d_E[i] = psum * (1.0f / (float)DOUT);

    float* HPp = d_HP + (size_t)i * DOUT;
#pragma unroll
    for (int j = 0; j < 8; j++) {
        int idx = lane + 32 * j;
        if (idx < DOUT) HPp[idx] = o[j];
    }
}

// ---------------------------------------------------------------------------
// 4) per-graph softmax over nodes + weighted output; writes d_out directly
// ---------------------------------------------------------------------------
__global__ __launch_bounds__(128) void finalize_kernel(float* __restrict__ out) {
    __shared__ float sh[128];
    __shared__ float alpha_sh[NODESG];
    int g = blockIdx.x;
    int tid = threadIdx.x;

    float ev = (tid < NODESG) ? d_E[g * NODESG + tid] : -3.4e38f;
    sh[tid] = ev;
    __syncthreads();
#pragma unroll
    for (int s = 64; s > 0; s >>= 1) {
        if (tid < s) sh[tid] = fmaxf(sh[tid], sh[tid + s]);
        __syncthreads();
    }
    float m = sh[0];
    __syncthreads();

    float ex = (tid < NODESG) ? __expf(ev - m) : 0.0f;
    sh[tid] = ex;
    __syncthreads();
#pragma unroll
    for (int s = 64; s > 0; s >>= 1) {
        if (tid < s) sh[tid] += sh[tid + s];
        __syncthreads();
    }
    float inv = 1.0f / sh[0];

    float a = ex * inv;
    if (tid < NODESG) {
        out[g * NODESG + tid] = a;
        alpha_sh[tid] = a;
    }
    __syncthreads();

    const float* src = d_HP + (size_t)g * (NODESG * DOUT);
    float*       dst = out + NTOT + (size_t)g * (NODESG * DOUT);
    for (int idx = tid; idx < NODESG * DOUT; idx += 128) {
        dst[idx] = alpha_sh[idx / DOUT] * src[idx];
    }
}

// ---------------------------------------------------------------------------
extern "C" void kernel_launch(void* const* d_in, const int* in_sizes, int n_in,
                              void* d_out, int out_size) {
    const float* h  = (const float*)d_in[0];
    const int*   ei = (const int*)d_in[1];
    // d_in[2] = batch_index (unused: batch = i / 116 by construction)
    const float* Wq = (const float*)d_in[3];
    const float* Wk = (const float*)d_in[4];
    const float* Wv = (const float*)d_in[5];
    const float* Ws = (const float*)d_in[6];
    float* out = (float*)d_out;

    cudaFuncSetAttribute(gemm_mma_kernel,
                         cudaFuncAttributeMaxDynamicSharedMemorySize, GEMM_SMEM);

    void* flag_ptr = nullptr;
    cudaGetSymbolAddress(&flag_ptr, d_is32);
    cudaMemsetAsync(flag_ptr, 0, sizeof(int));

    detect_kernel<<<16, 256>>>(ei);
    pack_kernel<<<(PSTRIDE * HIDD + 255) / 256, 256>>>(Wq, Wk, Wv, Ws);
    aprep_kernel<<<(NTOT * HIDD + 255) / 256, 256>>>(h);

    dim3 gg(PSTRIDE / BN, NTOT / BM);   // x=8 (ncol, fastest -> A reuse), y=464
    gemm_mma_kernel<<<gg, 256, GEMM_SMEM>>>();

    attn_kernel<<<NTOT / 8, 256>>>(ei);

    finalize_kernel<<<BGRAPH, 128>>>(out);
}